// round 1
// baseline (speedup 1.0000x reference)
#include <cuda_runtime.h>

// ---------------- weights in constant memory (uniform access -> LDCU) ----------------
__constant__ float c_w11[8 * 3];        // (8,1,3)
__constant__ float c_b11[8];
__constant__ float c_w12[8 * 8 * 3];    // (8,8,3)
__constant__ float c_b12[8];
__constant__ float c_w21[16 * 8 * 3];   // (16,8,3)
__constant__ float c_b21[16];
__constant__ float c_w22[16 * 16 * 3];  // (16,16,3)
__constant__ float c_b22[16];
__constant__ float c_Wl[24 * 96];       // (24,96)
__constant__ float c_bl[24];

// h1(j) = relu(conv11(x))[.,j], zero-padded K=3 conv on 1 input channel
__device__ __forceinline__ void h1_compute(const float xv[24], int j, float dst[8]) {
#pragma unroll
    for (int c = 0; c < 8; c++) {
        float v = c_b11[c];
        if (j > 0)  v = fmaf(c_w11[c * 3 + 0], xv[j - 1], v);
        v = fmaf(c_w11[c * 3 + 1], xv[j], v);
        if (j < 23) v = fmaf(c_w11[c * 3 + 2], xv[j + 1], v);
        dst[c] = fmaxf(v, 0.0f);
    }
}

// h3(j) = relu(conv21(p1))[.,j], p1 is the pooled (8,12) activation
__device__ __forceinline__ void h3_compute(const float p1[8][12], int j, float dst[16]) {
#pragma unroll
    for (int c = 0; c < 16; c++) {
        float v = c_b21[c];
#pragma unroll
        for (int ci = 0; ci < 8; ci++) {
            if (j > 0)  v = fmaf(c_w21[(c * 8 + ci) * 3 + 0], p1[ci][j - 1], v);
            v = fmaf(c_w21[(c * 8 + ci) * 3 + 1], p1[ci][j], v);
            if (j < 11) v = fmaf(c_w21[(c * 8 + ci) * 3 + 2], p1[ci][j + 1], v);
        }
        dst[c] = fmaxf(v, 0.0f);
    }
}

__global__ void __launch_bounds__(128)
cnn_pre_lstm_kernel(const float* __restrict__ x, float* __restrict__ out, int nSamples) {
    int s = blockIdx.x * blockDim.x + threadIdx.x;
    if (s >= nSamples) return;

    // ---- load input sample (24 floats, 16B aligned) ----
    float xv[24];
    {
        const float4* xg = reinterpret_cast<const float4*>(x + (size_t)s * 24);
#pragma unroll
        for (int i = 0; i < 6; i++) {
            float4 v = xg[i];
            xv[4 * i + 0] = v.x; xv[4 * i + 1] = v.y;
            xv[4 * i + 2] = v.z; xv[4 * i + 3] = v.w;
        }
    }

    // ---- stage A: conv11 -> relu -> conv12 -> relu -> maxpool2  => p1[8][12] ----
    float p1[8][12];
    {
        float ring[3][8];             // h1 at 3 consecutive positions
        h1_compute(xv, 0, ring[0]);
        h1_compute(xv, 1, ring[1]);
#pragma unroll
        for (int j = 0; j < 24; j++) {
            float hA[8], hB[8], hC[8];
#pragma unroll
            for (int c = 0; c < 8; c++) {
                hA[c] = (j == 0)  ? 0.0f : ring[(j + 2) % 3][c];   // h1(j-1)
                hB[c] = ring[j % 3][c];                            // h1(j)
                hC[c] = (j == 23) ? 0.0f : ring[(j + 1) % 3][c];   // h1(j+1)
            }
#pragma unroll
            for (int co = 0; co < 8; co++) {
                float v = c_b12[co];
#pragma unroll
                for (int ci = 0; ci < 8; ci++) {
                    v = fmaf(c_w12[(co * 8 + ci) * 3 + 0], hA[ci], v);
                    v = fmaf(c_w12[(co * 8 + ci) * 3 + 1], hB[ci], v);
                    v = fmaf(c_w12[(co * 8 + ci) * 3 + 2], hC[ci], v);
                }
                v = fmaxf(v, 0.0f);
                if ((j & 1) == 0) p1[co][j >> 1] = v;
                else              p1[co][j >> 1] = fmaxf(p1[co][j >> 1], v);
            }
            if (j + 2 < 24) h1_compute(xv, j + 2, ring[(j + 2) % 3]);
        }
    }

    // ---- stage B: conv21 -> relu -> conv22 -> relu -> maxpool2  => p2[16][6] ----
    float p2[16][6];
    {
        float ring2[3][16];           // h3 at 3 consecutive positions
        h3_compute(p1, 0, ring2[0]);
        h3_compute(p1, 1, ring2[1]);
#pragma unroll
        for (int j = 0; j < 12; j++) {
            float gA[16], gB[16], gC[16];
#pragma unroll
            for (int c = 0; c < 16; c++) {
                gA[c] = (j == 0)  ? 0.0f : ring2[(j + 2) % 3][c];  // h3(j-1)
                gB[c] = ring2[j % 3][c];                           // h3(j)
                gC[c] = (j == 11) ? 0.0f : ring2[(j + 1) % 3][c];  // h3(j+1)
            }
#pragma unroll
            for (int co = 0; co < 16; co++) {
                float v = c_b22[co];
#pragma unroll
                for (int ci = 0; ci < 16; ci++) {
                    v = fmaf(c_w22[(co * 16 + ci) * 3 + 0], gA[ci], v);
                    v = fmaf(c_w22[(co * 16 + ci) * 3 + 1], gB[ci], v);
                    v = fmaf(c_w22[(co * 16 + ci) * 3 + 2], gC[ci], v);
                }
                v = fmaxf(v, 0.0f);
                if ((j & 1) == 0) p2[co][j >> 1] = v;
                else              p2[co][j >> 1] = fmaxf(p2[co][j >> 1], v);
            }
            if (j + 2 < 12) h3_compute(p1, j + 2, ring2[(j + 2) % 3]);
        }
    }

    // ---- stage C: linear (96 -> 24), feature index k = ch*6 + pos ----
    float acc[24];
#pragma unroll
    for (int o = 0; o < 24; o++) acc[o] = c_bl[o];
#pragma unroll
    for (int ch = 0; ch < 16; ch++) {
#pragma unroll
        for (int pos = 0; pos < 6; pos++) {
            float v = p2[ch][pos];
            int k = ch * 6 + pos;
#pragma unroll
            for (int o = 0; o < 24; o++)
                acc[o] = fmaf(c_Wl[o * 96 + k], v, acc[o]);
        }
    }

    // ---- store output sample (24 floats) ----
    {
        float4* og = reinterpret_cast<float4*>(out + (size_t)s * 24);
#pragma unroll
        for (int i = 0; i < 6; i++) {
            og[i] = make_float4(acc[4 * i + 0], acc[4 * i + 1],
                                acc[4 * i + 2], acc[4 * i + 3]);
        }
    }
}

extern "C" void kernel_launch(void* const* d_in, const int* in_sizes, int n_in,
                              void* d_out, int out_size) {
    const float* x = (const float*)d_in[0];

    // upload weights into constant memory (D2D async, graph-capturable)
    cudaMemcpyToSymbolAsync(c_w11, d_in[1],  8 * 3 * sizeof(float),      0, cudaMemcpyDeviceToDevice, 0);
    cudaMemcpyToSymbolAsync(c_b11, d_in[2],  8 * sizeof(float),          0, cudaMemcpyDeviceToDevice, 0);
    cudaMemcpyToSymbolAsync(c_w12, d_in[3],  8 * 8 * 3 * sizeof(float),  0, cudaMemcpyDeviceToDevice, 0);
    cudaMemcpyToSymbolAsync(c_b12, d_in[4],  8 * sizeof(float),          0, cudaMemcpyDeviceToDevice, 0);
    cudaMemcpyToSymbolAsync(c_w21, d_in[5],  16 * 8 * 3 * sizeof(float), 0, cudaMemcpyDeviceToDevice, 0);
    cudaMemcpyToSymbolAsync(c_b21, d_in[6],  16 * sizeof(float),         0, cudaMemcpyDeviceToDevice, 0);
    cudaMemcpyToSymbolAsync(c_w22, d_in[7],  16 * 16 * 3 * sizeof(float),0, cudaMemcpyDeviceToDevice, 0);
    cudaMemcpyToSymbolAsync(c_b22, d_in[8],  16 * sizeof(float),         0, cudaMemcpyDeviceToDevice, 0);
    cudaMemcpyToSymbolAsync(c_Wl,  d_in[9],  24 * 96 * sizeof(float),    0, cudaMemcpyDeviceToDevice, 0);
    cudaMemcpyToSymbolAsync(c_bl,  d_in[10], 24 * sizeof(float),         0, cudaMemcpyDeviceToDevice, 0);

    int nSamples = in_sizes[0] / 24;   // 512*256 = 131072
    int threads = 128;
    int blocks = (nSamples + threads - 1) / threads;
    cnn_pre_lstm_kernel<<<blocks, threads>>>(x, (float*)d_out, nSamples);
}